// round 11
// baseline (speedup 1.0000x reference)
#include <cuda_runtime.h>
#include <cstdint>

#define BATCH 512
#define TLEN  1024
#define NST   64

typedef unsigned long long ull;

// Packed f32x2 helpers (Blackwell FFMA2 path — only reachable via PTX f32x2)
#define FMA2(d, a, b, c) asm("fma.rn.f32x2 %0, %1, %2, %3;" : "=l"(d) : "l"(a), "l"(b), "l"(c))
#define ADD2(d, a, b)    asm("add.rn.f32x2 %0, %1, %2;"     : "=l"(d) : "l"(a), "l"(b))
#define UNPACK2(lo, hi, s) asm("mov.b64 {%0, %1}, %2;"      : "=f"(lo), "=f"(hi) : "l"(s))

#define CHAIN_BAR(q) asm volatile("bar.sync %0, 64;" :: "r"(1 + (q)) : "memory")

__device__ __forceinline__ float fexp(float x) {
    float y;
    asm("ex2.approx.f32 %0, %1;" : "=f"(y) : "f"(x * 1.4426950408889634f));
    return y;
}
__device__ __forceinline__ float ex2f(float x) {
    float y;
    asm("ex2.approx.f32 %0, %1;" : "=f"(y) : "f"(x));
    return y;
}
__device__ __forceinline__ float flog(float x) {
    float y;
    asm("lg2.approx.f32 %0, %1;" : "=f"(y) : "f"(x));
    return y * 0.6931471805599453f;
}

// chain index by descending-length rank
__device__ int g_perm[BATCH];

// Bitonic argsort of lengths (ascending), then store descending perm.
// Keys are (len<<16)|idx -> unique -> fully deterministic.
__global__ void sort_kernel(const int* __restrict__ lengths) {
    __shared__ unsigned key[BATCH];
    int t = threadIdx.x;
    int len = lengths[t];
    if (len < 1) len = 1;
    key[t] = ((unsigned)len << 16) | (unsigned)t;
    __syncthreads();
    for (int k = 2; k <= BATCH; k <<= 1) {
        for (int j = k >> 1; j > 0; j >>= 1) {
            int ix = t ^ j;
            if (ix > t) {
                unsigned a = key[t], b = key[ix];
                bool up = ((t & k) == 0);
                if (up ? (a > b) : (a < b)) { key[t] = b; key[ix] = a; }
            }
            __syncthreads();
        }
    }
    g_perm[BATCH - 1 - t] = (int)(key[t] & 0xFFFFu);  // descending by length
}

// grid=128, block=256: ONE CTA per SM. 4 chains/CTA; chain q = warps {2q,2q+1}.
// Anti-paired ranks: each SMSP pair hosts (long, short) -> long chain runs solo.
// Split matvec: own-warp half of w is readable after __syncwarp (pre-barrier);
// only the peer half waits on the named barrier -> barrier+LDS latency hidden
// under 16 pre-barrier FFMA2s.
__global__ void __launch_bounds__(256, 1) crf_kernel(
    const float* __restrict__ unary,
    const int*   __restrict__ lengths,
    const float* __restrict__ trans,
    float*       __restrict__ out)
{
    const int tid  = threadIdx.x;
    const int q    = tid >> 6;           // chain slot 0..3
    const int t64  = tid & 63;           // thread within chain
    const int hw   = t64 >> 5;           // warp-half within chain (0/1)
    const int lane = tid & 31;
    const int c    = t64;                // my column

    // rank -> chain index (anti-paired scheduling)
    const int i = blockIdx.x;
    int rank;
    if (q == 0)      rank = 2 * i;                 // longest in CTA
    else if (q == 1) rank = 2 * i + 1;
    else if (q == 2) rank = (BATCH - 1) - 2 * i;   // shortest
    else             rank = (BATCH - 2) - 2 * i;
    const int b = g_perm[rank];

    // E column slice computed inline (no prep kernel):
    // cE[k] = ( exp(trans[2k][c]), exp(trans[2k+1][c]) ), 32 packed i-pairs
    ull cE[32];
    #pragma unroll
    for (int k = 0; k < 32; k++) {
        float e0 = expf(trans[(2 * k) * NST + c]);
        float e1 = expf(trans[(2 * k + 1) * NST + c]);
        ull pk;
        asm("mov.b64 %0, {%1, %2};" : "=l"(pk) : "f"(e0), "f"(e1));
        cE[k] = pk;
    }

    __shared__ __align__(16) float wbuf[4][2][NST];  // [chain][buf][col]
    __shared__ int   sexp[4];                         // [chain] lag-2 exponent
    __shared__ float ssum[4][2];                      // [chain][warp-half]

    int len = lengths[b];
    if (len < 1) len = 1;
    const float* ub = unary + (size_t)b * (TLEN * NST);
    const float* pc = ub + c;

    // w0 = exp(u0) for my column
    float w = fexp(pc[0]);
    wbuf[q][0][c] = w;

    int ktot = 0;
    // distance-3 register prefetch pipeline of this thread's unary column
    float uA = 0.f, uB = 0.f, uC = 0.f;
    if (len > 1) uA = pc[NST];
    uB = (len > 2) ? pc[2 * NST] : uA;
    uC = (len > 3) ? pc[3 * NST] : uB;
    const float* up = pc + (size_t)((len - 1 < 4) ? (len - 1) : 4) * NST;

    const float L2E = 1.4426950408889634f;
    int buf = 0;
    const int kbOwn  = 16 * hw;         // cE base for own-warp i-half
    const int kbPeer = 16 - 16 * hw;    // cE base for peer-warp i-half

    for (int t = 1; t < len; t++) {
        // ---- independent pre-work ----
        float kf = 0.0f;
        if ((t & 3) == 2 && t >= 6) {
            int e = sexp[q];
            ktot += e;
            kf = (float)e;
        }
        float eu = ex2f(fmaf(uA, L2E, -kf));   // MUFU off the critical path
        float unew = *up;
        up += (t + 4 < len) ? NST : 0;

        // ---- own-warp half: visible after cheap __syncwarp ----
        __syncwarp();
        const ulonglong2* Pown = (const ulonglong2*)&wbuf[q][buf][32 * hw];
        ull a0 = 0ull, a1 = 0ull, a2 = 0ull, a3 = 0ull;
        #pragma unroll
        for (int m = 0; m < 8; m += 2) {
            ulonglong2 x = Pown[m];
            ulonglong2 y = Pown[m + 1];
            FMA2(a0, x.x, cE[kbOwn + 2 * m + 0], a0);
            FMA2(a1, x.y, cE[kbOwn + 2 * m + 1], a1);
            FMA2(a2, y.x, cE[kbOwn + 2 * m + 2], a2);
            FMA2(a3, y.y, cE[kbOwn + 2 * m + 3], a3);
        }

        // ---- peer half: needs the cross-warp barrier ----
        CHAIN_BAR(q);
        const ulonglong2* Pp = (const ulonglong2*)&wbuf[q][buf][32 * (1 - hw)];
        ull a4 = 0ull, a5 = 0ull, a6 = 0ull, a7 = 0ull;
        #pragma unroll
        for (int m = 0; m < 8; m += 2) {
            ulonglong2 x = Pp[m];
            ulonglong2 y = Pp[m + 1];
            FMA2(a4, x.x, cE[kbPeer + 2 * m + 0], a4);
            FMA2(a5, x.y, cE[kbPeer + 2 * m + 1], a5);
            FMA2(a6, y.x, cE[kbPeer + 2 * m + 2], a6);
            FMA2(a7, y.y, cE[kbPeer + 2 * m + 3], a7);
        }
        ADD2(a0, a0, a1);
        ADD2(a2, a2, a3);
        ADD2(a4, a4, a5);
        ADD2(a6, a6, a7);
        ADD2(a0, a0, a2);
        ADD2(a4, a4, a6);
        ADD2(a0, a0, a4);
        float slo, shi;
        UNPACK2(slo, shi, a0);
        w = (slo + shi) * eu;

        // renorm publish: column-0 thread's exponent, applied at t+2
        if ((t & 3) == 0 && c == 0) {
            int e = ((__float_as_int(w) >> 23) & 255) - 127;
            e = min(max(e, -100), 100);
            sexp[q] = e;
        }

        wbuf[q][buf ^ 1][c] = w;
        uA = uB; uB = uC; uC = unew;
        buf ^= 1;
    }

    // out[b] = ktot*ln2 + log(sum_j w_j): warp reduce, combine 2 warps via smem
    float s = w;
    #pragma unroll
    for (int off = 16; off; off >>= 1)
        s += __shfl_xor_sync(0xffffffffu, s, off);
    if (lane == 0) ssum[q][hw] = s;
    CHAIN_BAR(q);
    if (c == 0)
        out[b] = (float)ktot * 0.6931471805599453f + flog(ssum[q][0] + ssum[q][1]);
}

extern "C" void kernel_launch(void* const* d_in, const int* in_sizes, int n_in,
                              void* d_out, int out_size) {
    const float* unary   = nullptr;
    const int*   lengths = nullptr;
    const float* trans   = nullptr;
    for (int i = 0; i < n_in; i++) {
        if (in_sizes[i] == BATCH * TLEN * NST) unary   = (const float*)d_in[i];
        else if (in_sizes[i] == BATCH)         lengths = (const int*)d_in[i];
        else if (in_sizes[i] == NST * NST)     trans   = (const float*)d_in[i];
    }
    sort_kernel<<<1, BATCH>>>(lengths);
    crf_kernel<<<BATCH / 4, 256>>>(unary, lengths, trans, (float*)d_out);
}

// round 12
// speedup vs baseline: 2.1427x; 2.1427x over previous
#include <cuda_runtime.h>
#include <cstdint>

#define BATCH 512
#define TLEN  1024
#define NST   64

typedef unsigned long long ull;

// Packed f32x2 helpers (Blackwell FFMA2 path — only reachable via PTX f32x2)
#define FMA2(d, a, b, c) asm("fma.rn.f32x2 %0, %1, %2, %3;" : "=l"(d) : "l"(a), "l"(b), "l"(c))
#define ADD2(d, a, b)    asm("add.rn.f32x2 %0, %1, %2;"     : "=l"(d) : "l"(a), "l"(b))
#define UNPACK2(lo, hi, s) asm("mov.b64 {%0, %1}, %2;"      : "=f"(lo), "=f"(hi) : "l"(s))

#define CHAIN_BAR(q) asm volatile("bar.sync %0, 64;" :: "r"(1 + (q)) : "memory")

__device__ __forceinline__ float fexp(float x) {
    float y;
    asm("ex2.approx.f32 %0, %1;" : "=f"(y) : "f"(x * 1.4426950408889634f));
    return y;
}
__device__ __forceinline__ float ex2f(float x) {
    float y;
    asm("ex2.approx.f32 %0, %1;" : "=f"(y) : "f"(x));
    return y;
}
__device__ __forceinline__ float flog(float x) {
    float y;
    asm("lg2.approx.f32 %0, %1;" : "=f"(y) : "f"(x));
    return y * 0.6931471805599453f;
}

// chain index by descending-length rank
__device__ int g_perm[BATCH];

// Bitonic argsort of lengths (ascending), then store descending perm.
// Keys are (len<<16)|idx -> unique -> fully deterministic.
__global__ void sort_kernel(const int* __restrict__ lengths) {
    __shared__ unsigned key[BATCH];
    int t = threadIdx.x;
    int len = lengths[t];
    if (len < 1) len = 1;
    key[t] = ((unsigned)len << 16) | (unsigned)t;
    __syncthreads();
    for (int k = 2; k <= BATCH; k <<= 1) {
        for (int j = k >> 1; j > 0; j >>= 1) {
            int ix = t ^ j;
            if (ix > t) {
                unsigned a = key[t], b = key[ix];
                bool up = ((t & k) == 0);
                if (up ? (a > b) : (a < b)) { key[t] = b; key[ix] = a; }
            }
            __syncthreads();
        }
    }
    g_perm[BATCH - 1 - t] = (int)(key[t] & 0xFFFFu);  // descending by length
}

// grid=128, block=256: ONE CTA per SM (no cross-CTA contention).
// 4 chains/CTA; chain q = threads [64q, 64q+64) = warps {2q,2q+1}:
//   q=0 -> SMSP {0,1}, q=1 -> {2,3}, q=2 -> {0,1}, q=3 -> {2,3}.
// Anti-paired ranks: each SMSP pair hosts (long, short); the partner of a
// long chain exits early -> long chain runs solo on its SMSP pair.
// Per-chain named barrier keeps early exit decoupled (R8 structure, proven).
__global__ void __launch_bounds__(256, 1) crf_kernel(
    const float* __restrict__ unary,
    const int*   __restrict__ lengths,
    const float* __restrict__ trans,
    float*       __restrict__ out)
{
    const int tid  = threadIdx.x;
    const int q    = tid >> 6;           // chain slot 0..3
    const int t64  = tid & 63;           // thread within chain
    const int hw   = t64 >> 5;           // warp-half within chain (0/1)
    const int lane = tid & 31;
    const int c    = t64;                // my column

    // rank -> chain index (anti-paired scheduling)
    const int i = blockIdx.x;
    int rank;
    if (q == 0)      rank = 2 * i;                 // longest in CTA
    else if (q == 1) rank = 2 * i + 1;
    else if (q == 2) rank = (BATCH - 1) - 2 * i;   // shortest
    else             rank = (BATCH - 2) - 2 * i;
    const int b = g_perm[rank];

    // E column slice computed inline (replaces the 7us serial prep launch):
    // cE[k] = ( exp(trans[2k][c]), exp(trans[2k+1][c]) ), 32 packed i-pairs
    ull cE[32];
    #pragma unroll
    for (int k = 0; k < 32; k++) {
        float e0 = expf(trans[(2 * k) * NST + c]);
        float e1 = expf(trans[(2 * k + 1) * NST + c]);
        ull pk;
        asm("mov.b64 %0, {%1, %2};" : "=l"(pk) : "f"(e0), "f"(e1));
        cE[k] = pk;
    }

    __shared__ __align__(16) float wbuf[4][2][NST];  // [chain][buf][col]
    __shared__ int   sexp[4];                         // [chain] lag-2 exponent
    __shared__ float ssum[4][2];                      // [chain][warp-half]

    int len = lengths[b];
    if (len < 1) len = 1;
    const float* ub = unary + (size_t)b * (TLEN * NST);
    const float* pc = ub + c;

    // w0 = exp(u0) for my column
    float w = fexp(pc[0]);
    wbuf[q][0][c] = w;

    int ktot = 0;
    // distance-3 register prefetch pipeline of this thread's unary column
    float uA = 0.f, uB = 0.f, uC = 0.f;
    if (len > 1) uA = pc[NST];
    uB = (len > 2) ? pc[2 * NST] : uA;
    uC = (len > 3) ? pc[3 * NST] : uB;
    const float* up = pc + (size_t)((len - 1 < 4) ? (len - 1) : 4) * NST;

    const float L2E = 1.4426950408889634f;
    int buf = 0;

    for (int t = 1; t < len; t++) {
        CHAIN_BAR(q);

        // lagged renorm apply (published 2 steps ago), folded into the MUFU arg
        float kf = 0.0f;
        if ((t & 3) == 2 && t >= 6) {
            int e = sexp[q];
            ktot += e;
            kf = (float)e;
        }
        // hoisted before the FFMA stream so MUFU latency hides under it
        float eu = ex2f(fmaf(uA, L2E, -kf));

        // matvec for my column: 16 broadcast LDS.128 + 32 FFMA2, 8 accumulators
        const ulonglong2* P = (const ulonglong2*)wbuf[q][buf];
        ull a0 = 0ull, a1 = 0ull, a2 = 0ull, a3 = 0ull;
        ull a4 = 0ull, a5 = 0ull, a6 = 0ull, a7 = 0ull;
        #pragma unroll
        for (int m = 0; m < 16; m += 4) {
            ulonglong2 x = P[m];
            ulonglong2 y = P[m + 1];
            ulonglong2 z = P[m + 2];
            ulonglong2 v = P[m + 3];
            FMA2(a0, x.x, cE[2 * m + 0], a0);
            FMA2(a1, x.y, cE[2 * m + 1], a1);
            FMA2(a2, y.x, cE[2 * m + 2], a2);
            FMA2(a3, y.y, cE[2 * m + 3], a3);
            FMA2(a4, z.x, cE[2 * m + 4], a4);
            FMA2(a5, z.y, cE[2 * m + 5], a5);
            FMA2(a6, v.x, cE[2 * m + 6], a6);
            FMA2(a7, v.y, cE[2 * m + 7], a7);
        }
        ADD2(a0, a0, a1);
        ADD2(a2, a2, a3);
        ADD2(a4, a4, a5);
        ADD2(a6, a6, a7);
        ADD2(a0, a0, a2);
        ADD2(a4, a4, a6);
        ADD2(a0, a0, a4);
        float slo, shi;
        UNPACK2(slo, shi, a0);
        w = (slo + shi) * eu;

        // shift unary pipeline (distance 3); selp-guarded pointer walk
        uA = uB; uB = uC;
        uC = *up;
        up += (t + 4 < len) ? NST : 0;

        // renorm publish: column-0 thread's exponent, applied at t+2
        if ((t & 3) == 0 && c == 0) {
            int e = ((__float_as_int(w) >> 23) & 255) - 127;
            e = min(max(e, -100), 100);
            sexp[q] = e;
        }

        wbuf[q][buf ^ 1][c] = w;
        buf ^= 1;
    }

    // out[b] = ktot*ln2 + log(sum_j w_j): warp reduce, combine 2 warps via smem
    float s = w;
    #pragma unroll
    for (int off = 16; off; off >>= 1)
        s += __shfl_xor_sync(0xffffffffu, s, off);
    if (lane == 0) ssum[q][hw] = s;
    CHAIN_BAR(q);
    if (c == 0)
        out[b] = (float)ktot * 0.6931471805599453f + flog(ssum[q][0] + ssum[q][1]);
}

extern "C" void kernel_launch(void* const* d_in, const int* in_sizes, int n_in,
                              void* d_out, int out_size) {
    const float* unary   = nullptr;
    const int*   lengths = nullptr;
    const float* trans   = nullptr;
    for (int i = 0; i < n_in; i++) {
        if (in_sizes[i] == BATCH * TLEN * NST) unary   = (const float*)d_in[i];
        else if (in_sizes[i] == BATCH)         lengths = (const int*)d_in[i];
        else if (in_sizes[i] == NST * NST)     trans   = (const float*)d_in[i];
    }
    sort_kernel<<<1, BATCH>>>(lengths);
    crf_kernel<<<BATCH / 4, 256>>>(unary, lengths, trans, (float*)d_out);
}